// round 16
// baseline (speedup 1.0000x reference)
#include <cuda_runtime.h>
#include <cstdint>

#define BATCH 64
#define TSEQ  1024
#define DK    64
#define MASK_FILL (-4294967295.0f)   // -2^32 + 1

// 16MB device scratch: K transposed to [b][d][k] (written every launch)
__device__ float g_KT[(size_t)BATCH * DK * TSEQ];

// ---------------- packed f32x2 helpers (Blackwell FFMA2 path) --------------
__device__ __forceinline__ unsigned long long pack2(float v) {
    unsigned long long r;
    unsigned u = __float_as_uint(v);
    asm("mov.b64 %0, {%1, %1};" : "=l"(r) : "r"(u));
    return r;
}
__device__ __forceinline__ void ffma2(unsigned long long& d,
                                      unsigned long long a,
                                      unsigned long long b) {
    asm("fma.rn.f32x2 %0, %1, %2, %3;" : "=l"(d) : "l"(a), "l"(b), "l"(d));
}
__device__ __forceinline__ float2 unpack2(unsigned long long p) {
    unsigned lo, hi;
    asm("mov.b64 {%0, %1}, %2;" : "=r"(lo), "=r"(hi) : "l"(p));
    return make_float2(__uint_as_float(lo), __uint_as_float(hi));
}
__device__ __forceinline__ void prefetch_l2(const void* p) {
    asm volatile("prefetch.global.L2 [%0];" :: "l"(p));
}

// ---------------------------------------------------------------------------
// Kernel 0: K[b][k][d] -> g_KT[b][d][k]  (one block per batch)
// ---------------------------------------------------------------------------
__global__ __launch_bounds__(512)
void transpose_k_kernel(const float* __restrict__ K)
{
    const int b = blockIdx.x;
    const float* Kb = K + (size_t)b * TSEQ * DK;
    float* KTb = g_KT + (size_t)b * DK * TSEQ;
    const int tid = threadIdx.x;

    #pragma unroll
    for (int it = 0; it < 8; ++it) {
        int idx = tid + 512 * it;     // 0..4095 4x4 blocks
        int kg  = idx & 255;          // 256 k-groups
        int dg  = idx >> 8;           // 16 d-groups
        int kk  = kg * 4;
        int d4  = dg * 4;
        float4 r0 = *(const float4*)(Kb + (kk + 0) * DK + d4);
        float4 r1 = *(const float4*)(Kb + (kk + 1) * DK + d4);
        float4 r2 = *(const float4*)(Kb + (kk + 2) * DK + d4);
        float4 r3 = *(const float4*)(Kb + (kk + 3) * DK + d4);
        *(float4*)(KTb + (size_t)(d4 + 0) * TSEQ + kk) = make_float4(r0.x, r1.x, r2.x, r3.x);
        *(float4*)(KTb + (size_t)(d4 + 1) * TSEQ + kk) = make_float4(r0.y, r1.y, r2.y, r3.y);
        *(float4*)(KTb + (size_t)(d4 + 2) * TSEQ + kk) = make_float4(r0.z, r1.z, r2.z, r3.z);
        *(float4*)(KTb + (size_t)(d4 + 3) * TSEQ + kk) = make_float4(r0.w, r1.w, r2.w, r3.w);
    }
}

// ---------------------------------------------------------------------------
// Kernel 1: attn = softmax(QK^T/8 - gf, masked) * query_mask
// R15 structure + L2 prefetch of gf/mask (per tile) and qmask (last tile),
// issued BEFORE the GEMM so the DRAM transfer drains under FFMA2.
// ---------------------------------------------------------------------------
#define K1_Q    32
#define K1_KT   512
#define NKT     (TSEQ / K1_KT)    // 2
#define KT_PITCH 520              // 512 + 8 pad (floats)
#define QD_PITCH 72               // 64 dup floats + 8 pad
#define SMEM1_FLOATS (DK*KT_PITCH + DK*QD_PITCH + 128)

__global__ __launch_bounds__(512, 1)
void attn_softmax_kernel(const float* __restrict__ Q,
                         const int*   __restrict__ mask,     // bool as int32
                         const float* __restrict__ qmask,
                         const float* __restrict__ gf,
                         float* __restrict__ attn_out)
{
    extern __shared__ float smem[];
    float* sKt   = smem;                      // [64 d][520] K^T tile
    float* sQdup = sKt + DK * KT_PITCH;       // [64 d][72]  Q transposed+dup'd
    float* sRedS = sQdup + DK * QD_PITCH;     // [32 rows][4 warps]

    const int b   = blockIdx.y;
    const int q0  = blockIdx.x * K1_Q;
    const int tid = threadIdx.x;

    const int rg = tid >> 7;         // 4 row groups (8 rows each) - warp-uniform
    const int cg = tid & 127;        // 128 col groups (4 cols each)
    const int qr = rg * 8;
    const int kc = cg * 4;
    const int lane = tid & 31;
    const int wp   = (tid >> 5) & 3; // warp index within row group (4)

    const float* KTb = g_KT + (size_t)b * DK * TSEQ;

    // Q tile [32q][64d] -> sQdup[d][2q] (transpose + duplicate each value)
    if (tid < 128) {
        const float* Qb = Q + ((size_t)b * TSEQ + q0) * DK;
        int qg = tid & 7;
        int dg = tid >> 3;
        int qq = qg * 4;
        int d4 = dg * 4;
        float4 r0 = *(const float4*)(Qb + (qq + 0) * DK + d4);
        float4 r1 = *(const float4*)(Qb + (qq + 1) * DK + d4);
        float4 r2 = *(const float4*)(Qb + (qq + 2) * DK + d4);
        float4 r3 = *(const float4*)(Qb + (qq + 3) * DK + d4);
        float* p0 = sQdup + (d4 + 0) * QD_PITCH + qq * 2;
        float* p1 = sQdup + (d4 + 1) * QD_PITCH + qq * 2;
        float* p2 = sQdup + (d4 + 2) * QD_PITCH + qq * 2;
        float* p3 = sQdup + (d4 + 3) * QD_PITCH + qq * 2;
        *(float4*)(p0)     = make_float4(r0.x, r0.x, r1.x, r1.x);
        *(float4*)(p0 + 4) = make_float4(r2.x, r2.x, r3.x, r3.x);
        *(float4*)(p1)     = make_float4(r0.y, r0.y, r1.y, r1.y);
        *(float4*)(p1 + 4) = make_float4(r2.y, r2.y, r3.y, r3.y);
        *(float4*)(p2)     = make_float4(r0.z, r0.z, r1.z, r1.z);
        *(float4*)(p2 + 4) = make_float4(r2.z, r2.z, r3.z, r3.z);
        *(float4*)(p3)     = make_float4(r0.w, r0.w, r1.w, r1.w);
        *(float4*)(p3 + 4) = make_float4(r2.w, r2.w, r3.w, r3.w);
    }

    float lg[NKT][8][4];             // logits (later exp'd) in registers

    #pragma unroll
    for (int kt = 0; kt < NKT; ++kt) {
        const int k0 = kt * K1_KT;

        // K^T tile [64 d][512 k]: straight coalesced float4 copy from g_KT
        #pragma unroll
        for (int it = 0; it < 16; ++it) {
            int idx = tid + 512 * it;    // 0..8191 float4 chunks
            int d   = idx >> 7;          // 0..63
            int c4  = (idx & 127) * 4;   // 0..508
            *(float4*)(sKt + d * KT_PITCH + c4) =
                *(const float4*)(KTb + (size_t)d * TSEQ + k0 + c4);
        }

        // L2 prefetch: this tile's gf/mask (consumed in epilogue after GEMM)
        #pragma unroll
        for (int i = 0; i < 8; ++i) {
            size_t base = ((size_t)b * TSEQ + (q0 + qr + i)) * TSEQ + k0 + kc;
            prefetch_l2(gf + base);
            prefetch_l2(mask + base);
        }
        // last tile: also prefetch qmask (consumed in writeback)
        if (kt == NKT - 1) {
            #pragma unroll
            for (int i = 0; i < 8; ++i) {
                size_t rowbase = ((size_t)b * TSEQ + (q0 + qr + i)) * TSEQ + kc;
                prefetch_l2(qmask + rowbase);
                prefetch_l2(qmask + rowbase + K1_KT);
            }
        }
        __syncthreads();

        // GEMM: 8q x 4k microtile, zero packs (Q pre-duplicated, broadcast)
        unsigned long long acc[8][2];
        #pragma unroll
        for (int i = 0; i < 8; ++i) { acc[i][0] = 0ull; acc[i][1] = 0ull; }

        #pragma unroll 8
        for (int d = 0; d < DK; ++d) {
            const float* qrow = sQdup + d * QD_PITCH + qr * 2;
            ulonglong2 a01 = *(const ulonglong2*)(qrow);        // q0,q1 dup'd
            ulonglong2 a23 = *(const ulonglong2*)(qrow + 4);    // q2,q3
            ulonglong2 a45 = *(const ulonglong2*)(qrow + 8);    // q4,q5
            ulonglong2 a67 = *(const ulonglong2*)(qrow + 12);   // q6,q7
            ulonglong2 bp  = *(const ulonglong2*)(sKt + d * KT_PITCH + kc);
            ffma2(acc[0][0], a01.x, bp.x); ffma2(acc[0][1], a01.x, bp.y);
            ffma2(acc[1][0], a01.y, bp.x); ffma2(acc[1][1], a01.y, bp.y);
            ffma2(acc[2][0], a23.x, bp.x); ffma2(acc[2][1], a23.x, bp.y);
            ffma2(acc[3][0], a23.y, bp.x); ffma2(acc[3][1], a23.y, bp.y);
            ffma2(acc[4][0], a45.x, bp.x); ffma2(acc[4][1], a45.x, bp.y);
            ffma2(acc[5][0], a45.y, bp.x); ffma2(acc[5][1], a45.y, bp.y);
            ffma2(acc[6][0], a67.x, bp.x); ffma2(acc[6][1], a67.x, bp.y);
            ffma2(acc[7][0], a67.y, bp.x); ffma2(acc[7][1], a67.y, bp.y);
        }

        // epilogue into logit registers (LDGs now L2 hits)
        #pragma unroll
        for (int i = 0; i < 8; ++i) {
            size_t base = ((size_t)b * TSEQ + (q0 + qr + i)) * TSEQ + k0 + kc;
            float4 g = *(const float4*)(gf + base);
            int4   m = *(const int4*)(mask + base);
            float2 p0 = unpack2(acc[i][0]);   // k kc, kc+1
            float2 p1 = unpack2(acc[i][1]);   // k kc+2, kc+3
            lg[kt][i][0] = m.x ? MASK_FILL : fmaf(p0.x, 0.125f, -g.x);
            lg[kt][i][1] = m.y ? MASK_FILL : fmaf(p0.y, 0.125f, -g.y);
            lg[kt][i][2] = m.z ? MASK_FILL : fmaf(p1.x, 0.125f, -g.z);
            lg[kt][i][3] = m.w ? MASK_FILL : fmaf(p1.y, 0.125f, -g.w);
        }
        if (kt + 1 < NKT) __syncthreads();   // protect sKt before next copy
    }

    // ------------- exp pass (unshifted) + row-sum reduction --------------
    float inv[8];
    #pragma unroll
    for (int i = 0; i < 8; ++i) {
        float s = 0.f;
        #pragma unroll
        for (int kt = 0; kt < NKT; ++kt) {
            #pragma unroll
            for (int c = 0; c < 4; ++c) {
                lg[kt][i][c] = __expf(lg[kt][i][c]);   // MASK_FILL -> 0
                s += lg[kt][i][c];
            }
        }
        #pragma unroll
        for (int off = 16; off > 0; off >>= 1)
            s += __shfl_xor_sync(0xffffffffu, s, off);
        inv[i] = s;
    }
    __syncthreads();
    if (lane == 0) {
        #pragma unroll
        for (int i = 0; i < 8; ++i) sRedS[(qr + i) * 4 + wp] = inv[i];
    }
    __syncthreads();
    #pragma unroll
    for (int i = 0; i < 8; ++i) {
        const float* r = sRedS + (qr + i) * 4;
        inv[i] = 1.0f / ((r[0] + r[1]) + (r[2] + r[3]));
    }

    // normalize, * query_mask, write attn (float4, coalesced)
    #pragma unroll
    for (int i = 0; i < 8; ++i) {
        const size_t rowbase = ((size_t)b * TSEQ + (q0 + qr + i)) * TSEQ + kc;
        #pragma unroll
        for (int kt = 0; kt < NKT; ++kt) {
            const size_t off4 = rowbase + (size_t)kt * K1_KT;
            float4 qv = *(const float4*)(qmask + off4);
            float4 o;
            o.x = lg[kt][i][0] * qv.x * inv[i];
            o.y = lg[kt][i][1] * qv.y * inv[i];
            o.z = lg[kt][i][2] * qv.z * inv[i];
            o.w = lg[kt][i][3] * qv.w * inv[i];
            *(float4*)(attn_out + off4) = o;
        }
    }
}

// ---------------------------------------------------------------------------
// Kernel 2: result = attn @ V  (exact round-4 configuration: 128q x 64d, occ 2)
// ---------------------------------------------------------------------------
#define SAT_PITCH 132   // 128 q + 4 pad
#define SV_PITCH  68    // 64 d + 4 pad
#define K2_KC     64
#define SMEM2_FLOATS (K2_KC*SAT_PITCH + K2_KC*SV_PITCH)

__global__ __launch_bounds__(256, 2)
void av_kernel(const float* __restrict__ V,
               const float* __restrict__ attn,
               float* __restrict__ out)
{
    extern __shared__ float smem2[];
    float* sAt = smem2;                    // [64 k][132 q]
    float* sV  = sAt + K2_KC * SAT_PITCH;  // [64 k][68 d]

    const int b   = blockIdx.y;
    const int q0  = blockIdx.x * 128;
    const int tid = threadIdx.x;
    const int rg  = tid >> 4;
    const int cg  = tid & 15;
    const int qr  = rg * 8;
    const int dc  = cg * 4;

    unsigned long long acc[4][4];
    #pragma unroll
    for (int p = 0; p < 4; ++p)
        #pragma unroll
        for (int c = 0; c < 4; ++c) acc[p][c] = 0ull;

    for (int kt = 0; kt < TSEQ / K2_KC; ++kt) {
        const int k0 = kt * K2_KC;

        // attn tile [128 q][64 k] -> transposed sAt[k][q] via 4x4 blocks
        #pragma unroll
        for (int it = 0; it < 2; ++it) {
            int e  = tid + 256 * it;
            int kg = e & 15;
            int qg = e >> 4;
            int kk = kg * 4;
            int qq = qg * 4;
            const float* Ab = attn + ((size_t)b * TSEQ + q0 + qq) * TSEQ + k0 + kk;
            float4 r0 = *(const float4*)(Ab + 0 * TSEQ);
            float4 r1 = *(const float4*)(Ab + 1 * TSEQ);
            float4 r2 = *(const float4*)(Ab + 2 * TSEQ);
            float4 r3 = *(const float4*)(Ab + 3 * TSEQ);
            *(float4*)(sAt + (kk + 0) * SAT_PITCH + qq) = make_float4(r0.x, r1.x, r2.x, r3.x);
            *(float4*)(sAt + (kk + 1) * SAT_PITCH + qq) = make_float4(r0.y, r1.y, r2.y, r3.y);
            *(float4*)(sAt + (kk + 2) * SAT_PITCH + qq) = make_float4(r0.z, r1.z, r2.z, r3.z);
            *(float4*)(sAt + (kk + 3) * SAT_PITCH + qq) = make_float4(r0.w, r1.w, r2.w, r3.w);
        }
        // V tile [64 k][64 d]
        #pragma unroll
        for (int i = 0; i < 4; ++i) {
            int e   = tid + 256 * i;
            int kk  = e >> 4;
            int dd4 = (e & 15) * 4;
            *(float4*)(sV + kk * SV_PITCH + dd4) =
                *(const float4*)(V + ((size_t)b * TSEQ + k0 + kk) * DK + dd4);
        }
        __syncthreads();

        #pragma unroll 8
        for (int k = 0; k < K2_KC; ++k) {
            ulonglong2 a01 = *(const ulonglong2*)(sAt + k * SAT_PITCH + qr);
            ulonglong2 a23 = *(const ulonglong2*)(sAt + k * SAT_PITCH + qr + 4);
            float4 bv = *(const float4*)(sV + k * SV_PITCH + dc);
            unsigned long long b0 = pack2(bv.x);
            unsigned long long b1 = pack2(bv.y);
            unsigned long long b2 = pack2(bv.z);
            unsigned long long b3 = pack2(bv.w);
            ffma2(acc[0][0], a01.x, b0); ffma2(acc[0][1], a01.x, b1);
            ffma2(acc[0][2], a01.x, b2); ffma2(acc[0][3], a01.x, b3);
            ffma2(acc[1][0], a01.y, b0); ffma2(acc[1][1], a01.y, b1);
            ffma2(acc[1][2], a01.y, b2); ffma2(acc[1][3], a01.y, b3);
            ffma2(acc[2][0], a23.x, b0); ffma2(acc[2][1], a23.x, b1);
            ffma2(acc[2][2], a23.x, b2); ffma2(acc[2][3], a23.x, b3);
            ffma2(acc[3][0], a23.y, b0); ffma2(acc[3][1], a23.y, b1);
            ffma2(acc[3][2], a23.y, b2); ffma2(acc[3][3], a23.y, b3);
        }
        __syncthreads();
    }

    #pragma unroll
    for (int p = 0; p < 4; ++p) {
        float2 v0 = unpack2(acc[p][0]);
        float2 v1 = unpack2(acc[p][1]);
        float2 v2 = unpack2(acc[p][2]);
        float2 v3 = unpack2(acc[p][3]);
        float* o0 = out + ((size_t)b * TSEQ + q0 + qr + p * 2 + 0) * DK + dc;
        float* o1 = out + ((size_t)b * TSEQ + q0 + qr + p * 2 + 1) * DK + dc;
        *(float4*)o0 = make_float4(v0.x, v1.x, v2.x, v3.x);
        *(float4*)o1 = make_float4(v0.y, v1.y, v2.y, v3.y);
    }
}

// ---------------------------------------------------------------------------
extern "C" void kernel_launch(void* const* d_in, const int* in_sizes, int n_in,
                              void* d_out, int out_size)
{
    const float* key   = (const float*)d_in[0];
    const float* value = (const float*)d_in[1];
    const float* query = (const float*)d_in[2];
    const int*   mask  = (const int*)d_in[3];     // bool -> int32
    const float* qmask = (const float*)d_in[4];
    const float* gf    = (const float*)d_in[5];

    float* result = (float*)d_out;                                  // [64,1024,64]
    float* attn   = result + (size_t)BATCH * TSEQ * DK;             // [64,1024,1024]

    const int smem1 = SMEM1_FLOATS * (int)sizeof(float);
    cudaFuncSetAttribute(attn_softmax_kernel,
                         cudaFuncAttributeMaxDynamicSharedMemorySize, smem1);
    const int smem2 = SMEM2_FLOATS * (int)sizeof(float);
    cudaFuncSetAttribute(av_kernel,
                         cudaFuncAttributeMaxDynamicSharedMemorySize, smem2);

    transpose_k_kernel<<<BATCH, 512>>>(key);

    dim3 grid1(TSEQ / K1_Q, BATCH);
    attn_softmax_kernel<<<grid1, 512, smem1>>>(query, mask, qmask, gf, attn);

    dim3 grid2(TSEQ / 128, BATCH);
    av_kernel<<<grid2, 256, smem2>>>(value, attn, result);
}

// round 17
// speedup vs baseline: 1.0772x; 1.0772x over previous
#include <cuda_runtime.h>
#include <cstdint>

#define BATCH 64
#define TSEQ  1024
#define DK    64
#define MASK_FILL (-4294967295.0f)   // -2^32 + 1

// 16MB device scratch: K transposed to [b][d][k] (written every launch)
__device__ float g_KT[(size_t)BATCH * DK * TSEQ];

// ---------------- packed f32x2 helpers (Blackwell FFMA2 path) --------------
__device__ __forceinline__ unsigned long long pack2(float v) {
    unsigned long long r;
    unsigned u = __float_as_uint(v);
    asm("mov.b64 %0, {%1, %1};" : "=l"(r) : "r"(u));
    return r;
}
__device__ __forceinline__ void ffma2(unsigned long long& d,
                                      unsigned long long a,
                                      unsigned long long b) {
    asm("fma.rn.f32x2 %0, %1, %2, %3;" : "=l"(d) : "l"(a), "l"(b), "l"(d));
}
__device__ __forceinline__ float2 unpack2(unsigned long long p) {
    unsigned lo, hi;
    asm("mov.b64 {%0, %1}, %2;" : "=r"(lo), "=r"(hi) : "l"(p));
    return make_float2(__uint_as_float(lo), __uint_as_float(hi));
}

// ---------------------------------------------------------------------------
// Kernel 0: K[b][k][d] -> g_KT[b][d][k]
// 4 blocks per batch (full-chip DRAM streaming), each handles 256 k rows.
// ---------------------------------------------------------------------------
__global__ __launch_bounds__(512)
void transpose_k_kernel(const float* __restrict__ K)
{
    const int b  = blockIdx.x >> 2;          // batch
    const int ks = (blockIdx.x & 3) * 256;   // k-slice start
    const float* Kb = K + ((size_t)b * TSEQ + ks) * DK;
    float* KTb = g_KT + (size_t)b * DK * TSEQ + ks;
    const int tid = threadIdx.x;

    #pragma unroll
    for (int it = 0; it < 2; ++it) {
        int idx = tid + 512 * it;     // 0..1023 4x4 blocks (256k x 64d / 16)
        int kg  = idx & 63;           // 64 k-groups
        int dg  = idx >> 6;           // 16 d-groups
        int kk  = kg * 4;
        int d4  = dg * 4;
        float4 r0 = *(const float4*)(Kb + (kk + 0) * DK + d4);
        float4 r1 = *(const float4*)(Kb + (kk + 1) * DK + d4);
        float4 r2 = *(const float4*)(Kb + (kk + 2) * DK + d4);
        float4 r3 = *(const float4*)(Kb + (kk + 3) * DK + d4);
        *(float4*)(KTb + (size_t)(d4 + 0) * TSEQ + kk) = make_float4(r0.x, r1.x, r2.x, r3.x);
        *(float4*)(KTb + (size_t)(d4 + 1) * TSEQ + kk) = make_float4(r0.y, r1.y, r2.y, r3.y);
        *(float4*)(KTb + (size_t)(d4 + 2) * TSEQ + kk) = make_float4(r0.z, r1.z, r2.z, r3.z);
        *(float4*)(KTb + (size_t)(d4 + 3) * TSEQ + kk) = make_float4(r0.w, r1.w, r2.w, r3.w);
    }
}

// ---------------------------------------------------------------------------
// Kernel 1: attn = softmax(QK^T/8 - gf, masked) * query_mask  (R15 exact)
// ---------------------------------------------------------------------------
#define K1_Q    32
#define K1_KT   512
#define NKT     (TSEQ / K1_KT)    // 2
#define KT_PITCH 520              // 512 + 8 pad (floats)
#define QD_PITCH 72               // 64 dup floats + 8 pad
#define SMEM1_FLOATS (DK*KT_PITCH + DK*QD_PITCH + 128)

__global__ __launch_bounds__(512, 1)
void attn_softmax_kernel(const float* __restrict__ Q,
                         const int*   __restrict__ mask,     // bool as int32
                         const float* __restrict__ qmask,
                         const float* __restrict__ gf,
                         float* __restrict__ attn_out)
{
    extern __shared__ float smem[];
    float* sKt   = smem;                      // [64 d][520] K^T tile
    float* sQdup = sKt + DK * KT_PITCH;       // [64 d][72]  Q transposed+dup'd
    float* sRedS = sQdup + DK * QD_PITCH;     // [32 rows][4 warps]

    const int b   = blockIdx.y;
    const int q0  = blockIdx.x * K1_Q;
    const int tid = threadIdx.x;

    const int rg = tid >> 7;         // 4 row groups (8 rows each) - warp-uniform
    const int cg = tid & 127;        // 128 col groups (4 cols each)
    const int qr = rg * 8;
    const int kc = cg * 4;
    const int lane = tid & 31;
    const int wp   = (tid >> 5) & 3; // warp index within row group (4)

    const float* KTb = g_KT + (size_t)b * DK * TSEQ;

    // Q tile [32q][64d] -> sQdup[d][2q] (transpose + duplicate each value)
    if (tid < 128) {
        const float* Qb = Q + ((size_t)b * TSEQ + q0) * DK;
        int qg = tid & 7;
        int dg = tid >> 3;
        int qq = qg * 4;
        int d4 = dg * 4;
        float4 r0 = *(const float4*)(Qb + (qq + 0) * DK + d4);
        float4 r1 = *(const float4*)(Qb + (qq + 1) * DK + d4);
        float4 r2 = *(const float4*)(Qb + (qq + 2) * DK + d4);
        float4 r3 = *(const float4*)(Qb + (qq + 3) * DK + d4);
        float* p0 = sQdup + (d4 + 0) * QD_PITCH + qq * 2;
        float* p1 = sQdup + (d4 + 1) * QD_PITCH + qq * 2;
        float* p2 = sQdup + (d4 + 2) * QD_PITCH + qq * 2;
        float* p3 = sQdup + (d4 + 3) * QD_PITCH + qq * 2;
        *(float4*)(p0)     = make_float4(r0.x, r0.x, r1.x, r1.x);
        *(float4*)(p0 + 4) = make_float4(r2.x, r2.x, r3.x, r3.x);
        *(float4*)(p1)     = make_float4(r0.y, r0.y, r1.y, r1.y);
        *(float4*)(p1 + 4) = make_float4(r2.y, r2.y, r3.y, r3.y);
        *(float4*)(p2)     = make_float4(r0.z, r0.z, r1.z, r1.z);
        *(float4*)(p2 + 4) = make_float4(r2.z, r2.z, r3.z, r3.z);
        *(float4*)(p3)     = make_float4(r0.w, r0.w, r1.w, r1.w);
        *(float4*)(p3 + 4) = make_float4(r2.w, r2.w, r3.w, r3.w);
    }

    float lg[NKT][8][4];             // logits (later exp'd) in registers

    #pragma unroll
    for (int kt = 0; kt < NKT; ++kt) {
        const int k0 = kt * K1_KT;

        // K^T tile [64 d][512 k]: straight coalesced float4 copy from g_KT
        #pragma unroll
        for (int it = 0; it < 16; ++it) {
            int idx = tid + 512 * it;    // 0..8191 float4 chunks
            int d   = idx >> 7;          // 0..63
            int c4  = (idx & 127) * 4;   // 0..508
            *(float4*)(sKt + d * KT_PITCH + c4) =
                *(const float4*)(KTb + (size_t)d * TSEQ + k0 + c4);
        }
        __syncthreads();

        // GEMM: 8q x 4k microtile, zero packs (Q pre-duplicated, broadcast)
        unsigned long long acc[8][2];
        #pragma unroll
        for (int i = 0; i < 8; ++i) { acc[i][0] = 0ull; acc[i][1] = 0ull; }

        #pragma unroll 8
        for (int d = 0; d < DK; ++d) {
            const float* qrow = sQdup + d * QD_PITCH + qr * 2;
            ulonglong2 a01 = *(const ulonglong2*)(qrow);        // q0,q1 dup'd
            ulonglong2 a23 = *(const ulonglong2*)(qrow + 4);    // q2,q3
            ulonglong2 a45 = *(const ulonglong2*)(qrow + 8);    // q4,q5
            ulonglong2 a67 = *(const ulonglong2*)(qrow + 12);   // q6,q7
            ulonglong2 bp  = *(const ulonglong2*)(sKt + d * KT_PITCH + kc);
            ffma2(acc[0][0], a01.x, bp.x); ffma2(acc[0][1], a01.x, bp.y);
            ffma2(acc[1][0], a01.y, bp.x); ffma2(acc[1][1], a01.y, bp.y);
            ffma2(acc[2][0], a23.x, bp.x); ffma2(acc[2][1], a23.x, bp.y);
            ffma2(acc[3][0], a23.y, bp.x); ffma2(acc[3][1], a23.y, bp.y);
            ffma2(acc[4][0], a45.x, bp.x); ffma2(acc[4][1], a45.x, bp.y);
            ffma2(acc[5][0], a45.y, bp.x); ffma2(acc[5][1], a45.y, bp.y);
            ffma2(acc[6][0], a67.x, bp.x); ffma2(acc[6][1], a67.x, bp.y);
            ffma2(acc[7][0], a67.y, bp.x); ffma2(acc[7][1], a67.y, bp.y);
        }

        // epilogue into logit registers
        #pragma unroll
        for (int i = 0; i < 8; ++i) {
            size_t base = ((size_t)b * TSEQ + (q0 + qr + i)) * TSEQ + k0 + kc;
            float4 g = *(const float4*)(gf + base);
            int4   m = *(const int4*)(mask + base);
            float2 p0 = unpack2(acc[i][0]);   // k kc, kc+1
            float2 p1 = unpack2(acc[i][1]);   // k kc+2, kc+3
            lg[kt][i][0] = m.x ? MASK_FILL : fmaf(p0.x, 0.125f, -g.x);
            lg[kt][i][1] = m.y ? MASK_FILL : fmaf(p0.y, 0.125f, -g.y);
            lg[kt][i][2] = m.z ? MASK_FILL : fmaf(p1.x, 0.125f, -g.z);
            lg[kt][i][3] = m.w ? MASK_FILL : fmaf(p1.y, 0.125f, -g.w);
        }
        if (kt + 1 < NKT) __syncthreads();   // protect sKt before next copy
    }

    // ------------- exp pass (unshifted) + row-sum reduction --------------
    float inv[8];
    #pragma unroll
    for (int i = 0; i < 8; ++i) {
        float s = 0.f;
        #pragma unroll
        for (int kt = 0; kt < NKT; ++kt) {
            #pragma unroll
            for (int c = 0; c < 4; ++c) {
                lg[kt][i][c] = __expf(lg[kt][i][c]);   // MASK_FILL -> 0
                s += lg[kt][i][c];
            }
        }
        #pragma unroll
        for (int off = 16; off > 0; off >>= 1)
            s += __shfl_xor_sync(0xffffffffu, s, off);
        inv[i] = s;
    }
    __syncthreads();
    if (lane == 0) {
        #pragma unroll
        for (int i = 0; i < 8; ++i) sRedS[(qr + i) * 4 + wp] = inv[i];
    }
    __syncthreads();
    #pragma unroll
    for (int i = 0; i < 8; ++i) {
        const float* r = sRedS + (qr + i) * 4;
        inv[i] = 1.0f / ((r[0] + r[1]) + (r[2] + r[3]));
    }

    // normalize, * query_mask, write attn (float4, coalesced)
    #pragma unroll
    for (int i = 0; i < 8; ++i) {
        const size_t rowbase = ((size_t)b * TSEQ + (q0 + qr + i)) * TSEQ + kc;
        #pragma unroll
        for (int kt = 0; kt < NKT; ++kt) {
            const size_t off4 = rowbase + (size_t)kt * K1_KT;
            float4 qv = *(const float4*)(qmask + off4);
            float4 o;
            o.x = lg[kt][i][0] * qv.x * inv[i];
            o.y = lg[kt][i][1] * qv.y * inv[i];
            o.z = lg[kt][i][2] * qv.z * inv[i];
            o.w = lg[kt][i][3] * qv.w * inv[i];
            *(float4*)(attn_out + off4) = o;
        }
    }
}

// ---------------------------------------------------------------------------
// Kernel 2: result = attn @ V  (round-4 config; unroll widened to 16)
// ---------------------------------------------------------------------------
#define SAT_PITCH 132   // 128 q + 4 pad
#define SV_PITCH  68    // 64 d + 4 pad
#define K2_KC     64
#define SMEM2_FLOATS (K2_KC*SAT_PITCH + K2_KC*SV_PITCH)

__global__ __launch_bounds__(256, 2)
void av_kernel(const float* __restrict__ V,
               const float* __restrict__ attn,
               float* __restrict__ out)
{
    extern __shared__ float smem2[];
    float* sAt = smem2;                    // [64 k][132 q]
    float* sV  = sAt + K2_KC * SAT_PITCH;  // [64 k][68 d]

    const int b   = blockIdx.y;
    const int q0  = blockIdx.x * 128;
    const int tid = threadIdx.x;
    const int rg  = tid >> 4;
    const int cg  = tid & 15;
    const int qr  = rg * 8;
    const int dc  = cg * 4;

    unsigned long long acc[4][4];
    #pragma unroll
    for (int p = 0; p < 4; ++p)
        #pragma unroll
        for (int c = 0; c < 4; ++c) acc[p][c] = 0ull;

    for (int kt = 0; kt < TSEQ / K2_KC; ++kt) {
        const int k0 = kt * K2_KC;

        // attn tile [128 q][64 k] -> transposed sAt[k][q] via 4x4 blocks
        #pragma unroll
        for (int it = 0; it < 2; ++it) {
            int e  = tid + 256 * it;
            int kg = e & 15;
            int qg = e >> 4;
            int kk = kg * 4;
            int qq = qg * 4;
            const float* Ab = attn + ((size_t)b * TSEQ + q0 + qq) * TSEQ + k0 + kk;
            float4 r0 = *(const float4*)(Ab + 0 * TSEQ);
            float4 r1 = *(const float4*)(Ab + 1 * TSEQ);
            float4 r2 = *(const float4*)(Ab + 2 * TSEQ);
            float4 r3 = *(const float4*)(Ab + 3 * TSEQ);
            *(float4*)(sAt + (kk + 0) * SAT_PITCH + qq) = make_float4(r0.x, r1.x, r2.x, r3.x);
            *(float4*)(sAt + (kk + 1) * SAT_PITCH + qq) = make_float4(r0.y, r1.y, r2.y, r3.y);
            *(float4*)(sAt + (kk + 2) * SAT_PITCH + qq) = make_float4(r0.z, r1.z, r2.z, r3.z);
            *(float4*)(sAt + (kk + 3) * SAT_PITCH + qq) = make_float4(r0.w, r1.w, r2.w, r3.w);
        }
        // V tile [64 k][64 d]
        #pragma unroll
        for (int i = 0; i < 4; ++i) {
            int e   = tid + 256 * i;
            int kk  = e >> 4;
            int dd4 = (e & 15) * 4;
            *(float4*)(sV + kk * SV_PITCH + dd4) =
                *(const float4*)(V + ((size_t)b * TSEQ + k0 + kk) * DK + dd4);
        }
        __syncthreads();

        #pragma unroll 16
        for (int k = 0; k < K2_KC; ++k) {
            ulonglong2 a01 = *(const ulonglong2*)(sAt + k * SAT_PITCH + qr);
            ulonglong2 a23 = *(const ulonglong2*)(sAt + k * SAT_PITCH + qr + 4);
            float4 bv = *(const float4*)(sV + k * SV_PITCH + dc);
            unsigned long long b0 = pack2(bv.x);
            unsigned long long b1 = pack2(bv.y);
            unsigned long long b2 = pack2(bv.z);
            unsigned long long b3 = pack2(bv.w);
            ffma2(acc[0][0], a01.x, b0); ffma2(acc[0][1], a01.x, b1);
            ffma2(acc[0][2], a01.x, b2); ffma2(acc[0][3], a01.x, b3);
            ffma2(acc[1][0], a01.y, b0); ffma2(acc[1][1], a01.y, b1);
            ffma2(acc[1][2], a01.y, b2); ffma2(acc[1][3], a01.y, b3);
            ffma2(acc[2][0], a23.x, b0); ffma2(acc[2][1], a23.x, b1);
            ffma2(acc[2][2], a23.x, b2); ffma2(acc[2][3], a23.x, b3);
            ffma2(acc[3][0], a23.y, b0); ffma2(acc[3][1], a23.y, b1);
            ffma2(acc[3][2], a23.y, b2); ffma2(acc[3][3], a23.y, b3);
        }
        __syncthreads();
    }

    #pragma unroll
    for (int p = 0; p < 4; ++p) {
        float2 v0 = unpack2(acc[p][0]);
        float2 v1 = unpack2(acc[p][1]);
        float2 v2 = unpack2(acc[p][2]);
        float2 v3 = unpack2(acc[p][3]);
        float* o0 = out + ((size_t)b * TSEQ + q0 + qr + p * 2 + 0) * DK + dc;
        float* o1 = out + ((size_t)b * TSEQ + q0 + qr + p * 2 + 1) * DK + dc;
        *(float4*)o0 = make_float4(v0.x, v1.x, v2.x, v3.x);
        *(float4*)o1 = make_float4(v0.y, v1.y, v2.y, v3.y);
    }
}

// ---------------------------------------------------------------------------
extern "C" void kernel_launch(void* const* d_in, const int* in_sizes, int n_in,
                              void* d_out, int out_size)
{
    const float* key   = (const float*)d_in[0];
    const float* value = (const float*)d_in[1];
    const float* query = (const float*)d_in[2];
    const int*   mask  = (const int*)d_in[3];     // bool -> int32
    const float* qmask = (const float*)d_in[4];
    const float* gf    = (const float*)d_in[5];

    float* result = (float*)d_out;                                  // [64,1024,64]
    float* attn   = result + (size_t)BATCH * TSEQ * DK;             // [64,1024,1024]

    const int smem1 = SMEM1_FLOATS * (int)sizeof(float);
    cudaFuncSetAttribute(attn_softmax_kernel,
                         cudaFuncAttributeMaxDynamicSharedMemorySize, smem1);
    const int smem2 = SMEM2_FLOATS * (int)sizeof(float);
    cudaFuncSetAttribute(av_kernel,
                         cudaFuncAttributeMaxDynamicSharedMemorySize, smem2);

    transpose_k_kernel<<<BATCH * 4, 512>>>(key);

    dim3 grid1(TSEQ / K1_Q, BATCH);
    attn_softmax_kernel<<<grid1, 512, smem1>>>(query, mask, qmask, gf, attn);

    dim3 grid2(TSEQ / 128, BATCH);
    av_kernel<<<grid2, 256, smem2>>>(value, attn, result);
}